// round 16
// baseline (speedup 1.0000x reference)
#include <cuda_runtime.h>
#include <cuda_bf16.h>
#include <math.h>
#include <stdint.h>

// Problem dims
#define ZD   4096
#define HID  1024
#define DEN  100
#define OUT_D 100
#define BATCH 8
#define WIN  512
#define ROWS (BATCH * WIN)      // 4096
#define G3   (3 * HID)          // 3072

// ---------------- scratch (__device__ globals; no allocation allowed) ------
__device__ __nv_bfloat16 g_zhi [ (size_t)ROWS * ZD ];
__device__ __nv_bfloat16 g_zlo [ (size_t)ROWS * ZD ];
__device__ __nv_bfloat16 g_Wlg_hi[ (size_t)ZD * ZD ];
__device__ __nv_bfloat16 g_Wlg_lo[ (size_t)ZD * ZD ];
__device__ __nv_bfloat16 g_WihT_hi[ (size_t)G3 * ZD ];
__device__ __nv_bfloat16 g_WihT_lo[ (size_t)G3 * ZD ];
__device__ __nv_bfloat16 g_WcT_hi[ (size_t)G3 * ZD ];
__device__ __nv_bfloat16 g_WcT_lo[ (size_t)G3 * ZD ];
__device__ float g_GI  [ (size_t)ROWS * G3 ];
__device__ float g_bcomb[G3];
__device__ float g_zb  [ZD];                             // stays zero
__device__ float g_H   [ (size_t)ROWS * HID ];
__device__ float g_D   [ (size_t)ROWS * DEN ];
__device__ float g_hT  [2][HID * BATCH];                 // ping-pong h, [k][b]

// Hierarchical grid barrier: 8 group counters (256B apart; L2 bit-7 is
// transparent so 128B strides would pair-collide) + 1 global counter +
// once-written sense flag (R11-proven topology).
#define NCTA_SCAN 128
#define NGRP      8
#define GRP_SZ    16
__device__ unsigned g_ctr1[NGRP * 64];   // stride 64 uints = 256 B
__device__ unsigned g_ctr2 = 0;
__device__ volatile unsigned g_bar_flag = 0;

// ---------------- helpers ---------------------------------------------------
__device__ __forceinline__ uint32_t smem_u32(const void* p) {
    uint32_t a;
    asm("{ .reg .u64 t; cvta.to.shared.u64 t, %1; cvt.u32.u64 %0, t; }"
        : "=r"(a) : "l"(p));
    return a;
}
__device__ __forceinline__ void cp16(uint32_t dst, const void* src) {
    asm volatile(
        "{ .reg .u64 g; cvta.to.global.u64 g, %1; "
        "cp.async.cg.shared.global [%0], [g], 16; }"
        :: "r"(dst), "l"(src) : "memory");
}
__device__ __forceinline__ void cp_commit() {
    asm volatile("cp.async.commit_group;" ::: "memory");
}
template <int N>
__device__ __forceinline__ void cp_wait() {
    asm volatile("cp.async.wait_group %0;" :: "n"(N) : "memory");
}
__device__ __forceinline__ void ldsm_x4(uint32_t* r, uint32_t addr) {
    asm volatile("ldmatrix.sync.aligned.m8n8.x4.shared.b16 {%0,%1,%2,%3}, [%4];"
        : "=r"(r[0]), "=r"(r[1]), "=r"(r[2]), "=r"(r[3]) : "r"(addr));
}
__device__ __forceinline__ void mma16816(float* d, const uint32_t* a,
                                         uint32_t b0, uint32_t b1) {
    asm volatile(
        "mma.sync.aligned.m16n8k16.row.col.f32.bf16.bf16.f32 "
        "{%0,%1,%2,%3}, {%4,%5,%6,%7}, {%8,%9}, {%0,%1,%2,%3};"
        : "+f"(d[0]), "+f"(d[1]), "+f"(d[2]), "+f"(d[3])
        : "r"(a[0]), "r"(a[1]), "r"(a[2]), "r"(a[3]), "r"(b0), "r"(b1));
}
__device__ __forceinline__ void ffma2(unsigned long long& d,
                                      unsigned long long a, unsigned long long b) {
    asm("fma.rn.f32x2 %0, %1, %2, %3;" : "=l"(d) : "l"(a), "l"(b), "l"(d));
}
__device__ __forceinline__ unsigned long long splat2(float x) {
    unsigned long long r;
    asm("mov.b64 %0, {%1, %1};" : "=l"(r) : "r"(__float_as_uint(x)));
    return r;
}
__device__ __forceinline__ void unpack2(unsigned long long v, float& lo, float& hi) {
    uint32_t l, h;
    asm("mov.b64 {%0, %1}, %2;" : "=r"(l), "=r"(h) : "l"(v));
    lo = __uint_as_float(l);
    hi = __uint_as_float(h);
}
__device__ __forceinline__ float sel8(const float* a, int b) {
    float t0 = (b & 1) ? a[1] : a[0];
    float t1 = (b & 1) ? a[3] : a[2];
    float t2 = (b & 1) ? a[5] : a[4];
    float t3 = (b & 1) ? a[7] : a[6];
    float u0 = (b & 2) ? t1 : t0;
    float u1 = (b & 2) ? t3 : t2;
    return (b & 4) ? u1 : u0;
}
__device__ __forceinline__ uint32_t pack_bf(float a, float b) {
    return ((uint32_t)__bfloat16_as_ushort(__float2bfloat16(b)) << 16) |
           (uint32_t)__bfloat16_as_ushort(__float2bfloat16(a));
}

// ---------------- merged prep kernel ----------------------------------------
#define PREP_BLOCKS (1024 + 12288 + 1024 + 48)

__global__ __launch_bounds__(256) void prep_kernel(
    const float* __restrict__ Wlg, const float* __restrict__ Wih,
    const float* __restrict__ z,
    const float* __restrict__ b_lg, const float* __restrict__ b_ih)
{
    __shared__ float tile[32][33];
    const int bx = blockIdx.x;
    const int tid = threadIdx.x;

    if (bx < 1024) {
        const float4* src = (const float4*)Wlg;
        uint2* dh = (uint2*)g_Wlg_hi;
        uint2* dl = (uint2*)g_Wlg_lo;
        for (int i = bx * 256 + tid; i < ZD * ZD / 4; i += 1024 * 256) {
            float4 v = src[i];
            uint32_t h0 = pack_bf(v.x, v.y), h1 = pack_bf(v.z, v.w);
            float lx = v.x - __bfloat162float(__float2bfloat16(v.x));
            float ly = v.y - __bfloat162float(__float2bfloat16(v.y));
            float lz = v.z - __bfloat162float(__float2bfloat16(v.z));
            float lw = v.w - __bfloat162float(__float2bfloat16(v.w));
            dh[i] = make_uint2(h0, h1);
            dl[i] = make_uint2(pack_bf(lx, ly), pack_bf(lz, lw));
        }
    } else if (bx < 13312) {
        const int id = bx - 1024;
        const int tbx = id % (G3 / 32);
        const int tby = id / (G3 / 32);
        const int tx = tid & 31, ty = tid >> 5;
        const int x = tbx * 32 + tx;
        const int y0 = tby * 32;
        #pragma unroll
        for (int j = ty; j < 32; j += 8)
            tile[j][tx] = Wih[(size_t)(y0 + j) * G3 + x];
        __syncthreads();
        const int k = tby * 32 + tx;
        const int n0 = tbx * 32;
        #pragma unroll
        for (int j = ty; j < 32; j += 8) {
            float v = tile[tx][j];
            __nv_bfloat16 h = __float2bfloat16(v);
            size_t o = (size_t)(n0 + j) * ZD + k;
            g_WihT_hi[o] = h;
            g_WihT_lo[o] = __float2bfloat16(v - __bfloat162float(h));
        }
    } else if (bx < 14336) {
        const int b0 = bx - 13312;
        const float4* src = (const float4*)z;
        uint2* dh = (uint2*)g_zhi;
        uint2* dl = (uint2*)g_zlo;
        for (int i = b0 * 256 + tid; i < ROWS * ZD / 4; i += 1024 * 256) {
            float4 v = src[i];
            uint32_t h0 = pack_bf(v.x, v.y), h1 = pack_bf(v.z, v.w);
            float lx = v.x - __bfloat162float(__float2bfloat16(v.x));
            float ly = v.y - __bfloat162float(__float2bfloat16(v.y));
            float lz = v.z - __bfloat162float(__float2bfloat16(v.z));
            float lw = v.w - __bfloat162float(__float2bfloat16(v.w));
            dh[i] = make_uint2(h0, h1);
            dl[i] = make_uint2(pack_bf(lx, ly), pack_bf(lz, lw));
        }
    } else {
        __shared__ float red[4][64];
        const int bid = bx - 14336;
        const int tx = tid & 63;
        const int ty = tid >> 6;
        const int o = bid * 64 + tx;
        float acc = 0.0f;
        for (int m = ty; m < ZD; m += 4)
            acc = fmaf(b_lg[m], Wih[(size_t)m * G3 + o], acc);
        red[ty][tx] = acc;
        __syncthreads();
        if (ty == 0)
            g_bcomb[o] = b_ih[o] + red[0][tx] + red[1][tx] + red[2][tx] + red[3][tx];
    }
}

// ---------------- split-bf16 mma.sync GEMM (128x256 tile, 512 thr) ----------
#define MMK       ZD
#define BKC       32
#define NC        (MMK / BKC)      // 128 chunks
#define ROWB      80
#define A_TILEB   (128 * ROWB)
#define B_TILEB   (256 * ROWB)
#define STAGEB    (2 * A_TILEB + 2 * B_TILEB)  // 61440
#define NSTAGE    3
#define MM_SMEM   (NSTAGE * STAGEB)            // 184320

__global__ __launch_bounds__(512) void mm_mma_kernel(
    const __nv_bfloat16* __restrict__ Ahi, const __nv_bfloat16* __restrict__ Alo,
    const __nv_bfloat16* __restrict__ Bhi, const __nv_bfloat16* __restrict__ Blo,
    const float* __restrict__ bias,
    __nv_bfloat16* __restrict__ Chi, __nv_bfloat16* __restrict__ Clo,
    int Nglob, int which)
{
    extern __shared__ char smem[];
    const uint32_t sb = smem_u32(smem);
    const int tid  = threadIdx.x;
    const int wid  = tid >> 5;
    const int lane = tid & 31;
    const int wm   = wid & 3;
    const int wn   = wid >> 2;

    const size_t mBase = (size_t)blockIdx.y * 128;
    const size_t nBase = (size_t)blockIdx.x * 256;

    const __nv_bfloat16* tp[4] = { Ahi, Alo, Bhi, Blo };
    const size_t rb[4]  = { mBase, mBase, nBase, nBase };
    const uint32_t toff[4] = { 0, A_TILEB, 2 * A_TILEB, 2 * A_TILEB + B_TILEB };

    const __nv_bfloat16* srcs[6];
    uint32_t dsts[6];
    #pragma unroll
    for (int i = 0; i < 6; ++i) {
        const int u   = tid + 512 * i;
        const int r   = u >> 2;
        const int seg = u & 3;
        int tile, lrow;
        if (r < 128)      { tile = 0; lrow = r; }
        else if (r < 256) { tile = 1; lrow = r - 128; }
        else if (r < 512) { tile = 2; lrow = r - 256; }
        else              { tile = 3; lrow = r - 512; }
        srcs[i] = tp[tile] + (rb[tile] + lrow) * MMK + seg * 8;
        dsts[i] = toff[tile] + (uint32_t)lrow * ROWB + seg * 16;
    }

    float acc[2][8][4];
    #pragma unroll
    for (int a = 0; a < 2; ++a)
        #pragma unroll
        for (int b = 0; b < 8; ++b)
            #pragma unroll
            for (int c = 0; c < 4; ++c) acc[a][b][c] = 0.0f;

    const int arow = wm * 32 + (lane & 7) + 8 * ((lane >> 3) & 1);
    const int brow = wn * 64 + (lane & 7) + 8 * (lane >> 4);
    const int acol_half = lane >> 4;
    const int bcol_half = (lane >> 3) & 1;

    #pragma unroll
    for (int i = 0; i < 6; ++i) cp16(sb + 0 * STAGEB + dsts[i], srcs[i]);
    cp_commit();
    #pragma unroll
    for (int i = 0; i < 6; ++i) cp16(sb + 1 * STAGEB + dsts[i], srcs[i] + BKC);
    cp_commit();
    cp_wait<1>();
    __syncthreads();

    int s = 0;
    for (int c = 0; c < NC; ++c) {
        const uint32_t stB = sb + s * STAGEB;
        const int pf = (s + 2 >= NSTAGE) ? s + 2 - NSTAGE : s + 2;
        const uint32_t pfB = sb + pf * STAGEB;
        const bool do_pf = (c + 2 < NC);
        const size_t pfk = (size_t)(c + 2) * BKC;

        const uint32_t AhB = stB;
        const uint32_t AlB = stB + A_TILEB;
        const uint32_t BhB = stB + 2 * A_TILEB;
        const uint32_t BlB = stB + 2 * A_TILEB + B_TILEB;

        #pragma unroll
        for (int ks = 0; ks < 2; ++ks) {
            const uint32_t acolb = (uint32_t)(16 * ks + 8 * acol_half) * 2;
            const uint32_t bcolb = (uint32_t)(16 * ks + 8 * bcol_half) * 2;
            uint32_t Ah0[4], Ah1[4], Al0[4], Al1[4];
            ldsm_x4(Ah0, AhB + (uint32_t)arow * ROWB + acolb);
            ldsm_x4(Ah1, AhB + (uint32_t)(arow + 16) * ROWB + acolb);
            ldsm_x4(Al0, AlB + (uint32_t)arow * ROWB + acolb);
            ldsm_x4(Al1, AlB + (uint32_t)(arow + 16) * ROWB + acolb);
            #pragma unroll
            for (int nb = 0; nb < 4; ++nb) {
                const uint32_t brb = (uint32_t)(brow + nb * 16) * ROWB + bcolb;
                uint32_t bh[4], bl[4];
                ldsm_x4(bh, BhB + brb);
                ldsm_x4(bl, BlB + brb);
                {
                    const int g = ks * 4 + nb;
                    if (g < 6 && do_pf) cp16(pfB + dsts[g], srcs[g] + pfk);
                }
                mma16816(acc[0][2 * nb],     Ah0, bh[0], bh[1]);
                mma16816(acc[0][2 * nb + 1], Ah0, bh[2], bh[3]);
                mma16816(acc[1][2 * nb],     Ah1, bh[0], bh[1]);
                mma16816(acc[1][2 * nb + 1], Ah1, bh[2], bh[3]);
                mma16816(acc[0][2 * nb],     Ah0, bl[0], bl[1]);
                mma16816(acc[0][2 * nb + 1], Ah0, bl[2], bl[3]);
                mma16816(acc[1][2 * nb],     Ah1, bl[0], bl[1]);
                mma16816(acc[1][2 * nb + 1], Ah1, bl[2], bl[3]);
                mma16816(acc[0][2 * nb],     Al0, bh[0], bh[1]);
                mma16816(acc[0][2 * nb + 1], Al0, bh[2], bh[3]);
                mma16816(acc[1][2 * nb],     Al1, bh[0], bh[1]);
                mma16816(acc[1][2 * nb + 1], Al1, bh[2], bh[3]);
            }
        }
        cp_commit();
        cp_wait<1>();
        __syncthreads();
        s = (s + 1 == NSTAGE) ? 0 : s + 1;
    }

    const int rrow = (lane >> 2);
    const int ccol = 2 * (lane & 3);
    #pragma unroll
    for (int mi = 0; mi < 2; ++mi) {
        const size_t r0 = mBase + wm * 32 + mi * 16 + rrow;
        #pragma unroll
        for (int n8 = 0; n8 < 8; ++n8) {
            const int col = (int)nBase + wn * 64 + n8 * 8 + ccol;
            const float bz0 = __ldg(&bias[col]);
            const float bz1 = __ldg(&bias[col + 1]);
            const float* f = acc[mi][n8];
            if (which == 0) {
                #pragma unroll
                for (int h = 0; h < 2; ++h) {
                    const size_t r = r0 + 8 * h;
                    float v0 = f[2 * h]     + bz0;
                    float v1 = f[2 * h + 1] + bz1;
                    __nv_bfloat16 h0 = __float2bfloat16(v0);
                    __nv_bfloat16 h1 = __float2bfloat16(v1);
                    __nv_bfloat16 l0 = __float2bfloat16(v0 - __bfloat162float(h0));
                    __nv_bfloat16 l1 = __float2bfloat16(v1 - __bfloat162float(h1));
                    uint32_t hp = ((uint32_t)__bfloat16_as_ushort(h1) << 16) |
                                  (uint32_t)__bfloat16_as_ushort(h0);
                    uint32_t lp = ((uint32_t)__bfloat16_as_ushort(l1) << 16) |
                                  (uint32_t)__bfloat16_as_ushort(l0);
                    *(uint32_t*)&Chi[r * (size_t)Nglob + col] = hp;
                    *(uint32_t*)&Clo[r * (size_t)Nglob + col] = lp;
                }
            } else {
                #pragma unroll
                for (int h = 0; h < 2; ++h) {
                    const size_t r = r0 + 8 * h;
                    float2 v = make_float2(f[2 * h] + bz0, f[2 * h + 1] + bz1);
                    *(float2*)&g_GI[r * (size_t)Nglob + col] = v;
                }
            }
        }
    }
}

// ---------------- persistent GRU scan ---------------------------------------
__global__ __launch_bounds__(256, 1) void gru_scan_kernel(
    const float* __restrict__ W_hh, const float* __restrict__ b_hh)
{
    __shared__ alignas(16) float sh[HID * BATCH];    // h_prev, [k][b]
    __shared__ unsigned s_sense;
    const int tid  = threadIdx.x;
    const int lane = tid & 31;
    const int j = blockIdx.x * 8 + (tid >> 5);
    const int grp = blockIdx.x >> 4;                 // 8 groups of 16 CTAs

    // weights -> registers (full unroll => compile-time indices)
    float w0[32], w1[32], w2[32];
    #pragma unroll
    for (int it = 0; it < 32; ++it) {
        const size_t k = (size_t)(lane + 32 * it) * G3;
        w0[it] = __ldg(&W_hh[k + j]);
        w1[it] = __ldg(&W_hh[k + HID + j]);
        w2[it] = __ldg(&W_hh[k + 2 * HID + j]);
    }
    const float bh0 = b_hh[j];
    const float bh1 = b_hh[HID + j];
    const float bh2 = b_hh[2 * HID + j];

    if (tid == 0) s_sense = g_bar_flag;
    for (int i = tid; i < HID * BATCH; i += 256) sh[i] = 0.0f;   // h0 = 0
    __syncthreads();
    unsigned sense = s_sense;

    // prefetch gi for t = 0
    float pir = 0.f, piu = 0.f, pin = 0.f;
    if (lane < 8) {
        const float* gi = g_GI + (size_t)lane * WIN * G3;
        pir = gi[j]; piu = gi[HID + j]; pin = gi[2 * HID + j];
    }

    for (int t = 0; t < WIN; ++t) {
        unsigned long long A0[4], A1[4], A2[4];
        #pragma unroll
        for (int p = 0; p < 4; ++p) { A0[p] = 0ull; A1[p] = 0ull; A2[p] = 0ull; }

        #pragma unroll
        for (int it = 0; it < 32; ++it) {
            const int k = lane + 32 * it;
            const ulonglong2* hp = (const ulonglong2*)&sh[k * 8];
            const ulonglong2 hA = hp[0];
            const ulonglong2 hB = hp[1];
            const unsigned long long wr2 = splat2(w0[it]);
            const unsigned long long wu2 = splat2(w1[it]);
            const unsigned long long wn2 = splat2(w2[it]);
            ffma2(A0[0], wr2, hA.x); ffma2(A0[1], wr2, hA.y);
            ffma2(A0[2], wr2, hB.x); ffma2(A0[3], wr2, hB.y);
            ffma2(A1[0], wu2, hA.x); ffma2(A1[1], wu2, hA.y);
            ffma2(A1[2], wu2, hB.x); ffma2(A1[3], wu2, hB.y);
            ffma2(A2[0], wn2, hA.x); ffma2(A2[1], wn2, hA.y);
            ffma2(A2[2], wn2, hB.x); ffma2(A2[3], wn2, hB.y);
        }

        float a0[8], a1[8], a2[8];
        #pragma unroll
        for (int p = 0; p < 4; ++p) {
            unpack2(A0[p], a0[2 * p], a0[2 * p + 1]);
            unpack2(A1[p], a1[2 * p], a1[2 * p + 1]);
            unpack2(A2[p], a2[2 * p], a2[2 * p + 1]);
        }

        // stage A: butterfly within 8-lane groups (offsets 1,2,4)
        #pragma unroll
        for (int off = 1; off <= 4; off <<= 1) {
            #pragma unroll
            for (int b = 0; b < 8; ++b) {
                a0[b] += __shfl_xor_sync(0xffffffffu, a0[b], off);
                a1[b] += __shfl_xor_sync(0xffffffffu, a1[b], off);
                a2[b] += __shfl_xor_sync(0xffffffffu, a2[b], off);
            }
        }
        // stage B: pick batch b = lane&7, then reduce across groups
        const int bs = lane & 7;
        float hr = sel8(a0, bs);
        float hu = sel8(a1, bs);
        float hn = sel8(a2, bs);
        hr += __shfl_xor_sync(0xffffffffu, hr, 8);
        hu += __shfl_xor_sync(0xffffffffu, hu, 8);
        hn += __shfl_xor_sync(0xffffffffu, hn, 8);
        hr += __shfl_xor_sync(0xffffffffu, hr, 16);
        hu += __shfl_xor_sync(0xffffffffu, hu, 16);
        hn += __shfl_xor_sync(0xffffffffu, hn, 16);

        if (lane < 8) {
            hr += bh0; hu += bh1; hn += bh2;
            const float rg = 1.0f / (1.0f + expf(-(pir + hr)));
            const float ug = 1.0f / (1.0f + expf(-(piu + hu)));
            const float ng = tanhf(fmaf(rg, hn, pin));
            const float hp = sh[j * 8 + lane];
            const float hnew = (1.0f - ug) * ng + ug * hp;
            g_hT[t & 1][j * 8 + lane] = hnew;
            g_H[((size_t)lane * WIN + t) * HID + j] = hnew;
        }
        __syncthreads();

        // prefetch gi for step t+1 (independent of the barrier)
        float nir = 0.f, niu = 0.f, nin = 0.f;
        if (t + 1 < WIN && lane < 8) {
            const float* gi = g_GI + ((size_t)lane * WIN + t + 1) * G3;
            nir = gi[j]; niu = gi[HID + j]; nin = gi[2 * HID + j];
        }

        // hierarchical grid barrier: 16-way group arrivals in parallel,
        // then 8-way global, then once-written sense flag
        if (tid == 0) {
            __threadfence();
            const unsigned o1 = atomicAdd(&g_ctr1[grp * 64], 1u);
            if (o1 == GRP_SZ - 1) {
                g_ctr1[grp * 64] = 0u;
                __threadfence();
                const unsigned o2 = atomicAdd(&g_ctr2, 1u);
                if (o2 == NGRP - 1) {
                    g_ctr2 = 0u;
                    __threadfence();
                    g_bar_flag = sense ^ 1u;
                }
            }
            while (g_bar_flag == sense) { }
            __threadfence();
        }
        __syncthreads();
        sense ^= 1u;

        if (t + 1 < WIN) {
            const float4* src = (const float4*)g_hT[t & 1];
            float4* dst = (float4*)sh;
            #pragma unroll
            for (int i = tid; i < HID * BATCH / 4; i += 256) dst[i] = src[i];
            __syncthreads();
        }
        pir = nir; piu = niu; pin = nin;
    }
}

// ---------------- dense + heads (unchanged) --------------------------------
__global__ __launch_bounds__(128) void dense_kernel(
    const float* __restrict__ Wd, const float* __restrict__ bd)
{
    __shared__ float sh[8 * HID];
    const int r0 = blockIdx.x * 8;
    for (int i = threadIdx.x; i < 8 * HID; i += 128)
        sh[i] = g_H[(size_t)r0 * HID + i];
    __syncthreads();

    const int c = threadIdx.x;
    if (c < DEN) {
        float acc[8];
        #pragma unroll
        for (int i = 0; i < 8; ++i) acc[i] = bd[c];
        #pragma unroll 4
        for (int k = 0; k < HID; ++k) {
            const float w = Wd[k * DEN + c];
            #pragma unroll
            for (int i = 0; i < 8; ++i)
                acc[i] = fmaf(sh[i * HID + k], w, acc[i]);
        }
        #pragma unroll
        for (int i = 0; i < 8; ++i)
            g_D[(size_t)(r0 + i) * DEN + c] = acc[i];
    }
}

__global__ __launch_bounds__(128) void heads_kernel(
    const float* __restrict__ W_mu, const float* __restrict__ b_mu,
    const float* __restrict__ W_sg, const float* __restrict__ b_sg,
    const float* __restrict__ noise, float* __restrict__ out)
{
    __shared__ float sh[16 * DEN];
    const int r0 = blockIdx.x * 16;
    for (int i = threadIdx.x; i < 16 * DEN; i += 128)
        sh[i] = g_D[(size_t)r0 * DEN + i];
    __syncthreads();

    const int c = threadIdx.x;
    if (c < OUT_D) {
        float am[16], as[16];
        #pragma unroll
        for (int i = 0; i < 16; ++i) { am[i] = b_mu[c]; as[i] = b_sg[c]; }
        #pragma unroll 2
        for (int k = 0; k < DEN; ++k) {
            const float wm = W_mu[k * OUT_D + c];
            const float ws = W_sg[k * OUT_D + c];
            #pragma unroll
            for (int i = 0; i < 16; ++i) {
                const float d = sh[i * DEN + k];
                am[i] = fmaf(d, wm, am[i]);
                as[i] = fmaf(d, ws, as[i]);
            }
        }
        #pragma unroll
        for (int i = 0; i < 16; ++i) {
            const size_t r = (size_t)(r0 + i);
            const float x = as[i];
            const float sp = fmaxf(x, 0.0f) + log1pf(expf(-fabsf(x)));
            out[r * OUT_D + c] = fmaf(sp, noise[r * OUT_D + c], am[i]);
        }
    }
}

// ---------------------------------------------------------------------------
extern "C" void kernel_launch(void* const* d_in, const int* in_sizes, int n_in,
                              void* d_out, int out_size)
{
    const float* z        = (const float*)d_in[0];
    const float* noise    = (const float*)d_in[1];
    const float* W_lgssm  = (const float*)d_in[2];
    const float* b_lgssm  = (const float*)d_in[3];
    const float* W_ih     = (const float*)d_in[4];
    const float* b_ih     = (const float*)d_in[5];
    const float* W_hh     = (const float*)d_in[6];
    const float* b_hh     = (const float*)d_in[7];
    const float* W_dense  = (const float*)d_in[8];
    const float* b_dense  = (const float*)d_in[9];
    const float* W_mu     = (const float*)d_in[10];
    const float* b_mu     = (const float*)d_in[11];
    const float* W_sigma  = (const float*)d_in[12];
    const float* b_sigma  = (const float*)d_in[13];
    float* out = (float*)d_out;

    static int attr_done = 0;
    if (!attr_done) {
        cudaFuncSetAttribute(mm_mma_kernel,
                             cudaFuncAttributeMaxDynamicSharedMemorySize, MM_SMEM);
        attr_done = 1;
    }

    __nv_bfloat16 *p_zhi, *p_zlo, *p_Wlg_hi, *p_Wlg_lo, *p_Wih_hi, *p_Wih_lo;
    __nv_bfloat16 *p_WcT_hi, *p_WcT_lo;
    float *p_bcomb, *p_zb;
    cudaGetSymbolAddress((void**)&p_zhi,    g_zhi);
    cudaGetSymbolAddress((void**)&p_zlo,    g_zlo);
    cudaGetSymbolAddress((void**)&p_Wlg_hi, g_Wlg_hi);
    cudaGetSymbolAddress((void**)&p_Wlg_lo, g_Wlg_lo);
    cudaGetSymbolAddress((void**)&p_Wih_hi, g_WihT_hi);
    cudaGetSymbolAddress((void**)&p_Wih_lo, g_WihT_lo);
    cudaGetSymbolAddress((void**)&p_WcT_hi, g_WcT_hi);
    cudaGetSymbolAddress((void**)&p_WcT_lo, g_WcT_lo);
    cudaGetSymbolAddress((void**)&p_bcomb,  g_bcomb);
    cudaGetSymbolAddress((void**)&p_zb,     g_zb);

    // 1: merged prep (W_lgssm split | W_ih transpose+split | z split | bcomb)
    prep_kernel<<<PREP_BLOCKS, 256>>>(W_lgssm, W_ih, z, b_lgssm, b_ih);
    // 2: fold GEMM: W_combT = (W_lgssm @ W_ih)^T  -> bf16 hi/lo
    mm_mma_kernel<<<dim3(ZD / 256, G3 / 128), 512, MM_SMEM>>>(
        p_Wih_hi, p_Wih_lo, p_Wlg_hi, p_Wlg_lo, p_zb, p_WcT_hi, p_WcT_lo, ZD, 0);
    // 3: data GEMM: GI = z @ W_comb + b_comb -> fp32
    mm_mma_kernel<<<dim3(G3 / 256, ROWS / 128), 512, MM_SMEM>>>(
        p_zhi, p_zlo, p_WcT_hi, p_WcT_lo, p_bcomb, nullptr, nullptr, G3, 1);
    // 4: persistent GRU scan (ncu capture slot)
    gru_scan_kernel<<<NCTA_SCAN, 256>>>(W_hh, b_hh);
    // 5-6: deferred output path
    dense_kernel<<<ROWS / 8, 128>>>(W_dense, b_dense);
    heads_kernel<<<ROWS / 16, 128>>>(W_mu, b_mu, W_sigma, b_sigma, noise, out);
}

// round 17
// speedup vs baseline: 1.2262x; 1.2262x over previous
#include <cuda_runtime.h>
#include <cuda_bf16.h>
#include <math.h>
#include <stdint.h>

// Problem dims
#define ZD   4096
#define HID  1024
#define DEN  100
#define OUT_D 100
#define BATCH 8
#define WIN  512
#define ROWS (BATCH * WIN)      // 4096
#define G3   (3 * HID)          // 3072

typedef unsigned long long ull;

// ---------------- scratch (__device__ globals; no allocation allowed) ------
__device__ __nv_bfloat16 g_zhi [ (size_t)ROWS * ZD ];
__device__ __nv_bfloat16 g_zlo [ (size_t)ROWS * ZD ];
__device__ __nv_bfloat16 g_Wlg_hi[ (size_t)ZD * ZD ];
__device__ __nv_bfloat16 g_Wlg_lo[ (size_t)ZD * ZD ];
__device__ __nv_bfloat16 g_WihT_hi[ (size_t)G3 * ZD ];
__device__ __nv_bfloat16 g_WihT_lo[ (size_t)G3 * ZD ];
__device__ __nv_bfloat16 g_WcT_hi[ (size_t)G3 * ZD ];
__device__ __nv_bfloat16 g_WcT_lo[ (size_t)G3 * ZD ];
__device__ float g_GI  [ (size_t)ROWS * G3 ];
__device__ float g_bcomb[G3];
__device__ float g_zb  [ZD];                             // stays zero
__device__ float g_H   [ (size_t)ROWS * HID ];
__device__ float g_D   [ (size_t)ROWS * DEN ];
__device__ float g_hT  [2][HID * BATCH];                 // ping-pong h, [k][b]

// R11/R15 flat grid barrier (measured-best): arrival counter + polled flag
#define NCTA_SCAN 128
__device__ unsigned g_bar_ctr = 0;
__device__ volatile unsigned g_bar_flag = 0;

// ---------------- helpers ---------------------------------------------------
__device__ __forceinline__ uint32_t smem_u32(const void* p) {
    uint32_t a;
    asm("{ .reg .u64 t; cvta.to.shared.u64 t, %1; cvt.u32.u64 %0, t; }"
        : "=r"(a) : "l"(p));
    return a;
}
__device__ __forceinline__ void cp16(uint32_t dst, const void* src) {
    asm volatile(
        "{ .reg .u64 g; cvta.to.global.u64 g, %1; "
        "cp.async.cg.shared.global [%0], [g], 16; }"
        :: "r"(dst), "l"(src) : "memory");
}
__device__ __forceinline__ void cp_commit() {
    asm volatile("cp.async.commit_group;" ::: "memory");
}
template <int N>
__device__ __forceinline__ void cp_wait() {
    asm volatile("cp.async.wait_group %0;" :: "n"(N) : "memory");
}
__device__ __forceinline__ void ldsm_x4(uint32_t* r, uint32_t addr) {
    asm volatile("ldmatrix.sync.aligned.m8n8.x4.shared.b16 {%0,%1,%2,%3}, [%4];"
        : "=r"(r[0]), "=r"(r[1]), "=r"(r[2]), "=r"(r[3]) : "r"(addr));
}
__device__ __forceinline__ void mma16816(float* d, const uint32_t* a,
                                         uint32_t b0, uint32_t b1) {
    asm volatile(
        "mma.sync.aligned.m16n8k16.row.col.f32.bf16.bf16.f32 "
        "{%0,%1,%2,%3}, {%4,%5,%6,%7}, {%8,%9}, {%0,%1,%2,%3};"
        : "+f"(d[0]), "+f"(d[1]), "+f"(d[2]), "+f"(d[3])
        : "r"(a[0]), "r"(a[1]), "r"(a[2]), "r"(a[3]), "r"(b0), "r"(b1));
}
__device__ __forceinline__ void ffma2(ull& d, ull a, ull b) {
    asm("fma.rn.f32x2 %0, %1, %2, %3;" : "=l"(d) : "l"(a), "l"(b), "l"(d));
}
__device__ __forceinline__ ull splat2(float x) {
    ull r;
    asm("mov.b64 %0, {%1, %1};" : "=l"(r) : "r"(__float_as_uint(x)));
    return r;
}
__device__ __forceinline__ void unpack2(ull v, float& lo, float& hi) {
    uint32_t l, h;
    asm("mov.b64 {%0, %1}, %2;" : "=r"(l), "=r"(h) : "l"(v));
    lo = __uint_as_float(l);
    hi = __uint_as_float(h);
}
__device__ __forceinline__ float sel8(const float* a, int b) {
    float t0 = (b & 1) ? a[1] : a[0];
    float t1 = (b & 1) ? a[3] : a[2];
    float t2 = (b & 1) ? a[5] : a[4];
    float t3 = (b & 1) ? a[7] : a[6];
    float u0 = (b & 2) ? t1 : t0;
    float u1 = (b & 2) ? t3 : t2;
    return (b & 4) ? u1 : u0;
}
__device__ __forceinline__ uint32_t pack_bf(float a, float b) {
    return ((uint32_t)__bfloat16_as_ushort(__float2bfloat16(b)) << 16) |
           (uint32_t)__bfloat16_as_ushort(__float2bfloat16(a));
}

// ---------------- merged prep kernel ----------------------------------------
#define PREP_BLOCKS (1024 + 12288 + 1024 + 48)

__global__ __launch_bounds__(256) void prep_kernel(
    const float* __restrict__ Wlg, const float* __restrict__ Wih,
    const float* __restrict__ z,
    const float* __restrict__ b_lg, const float* __restrict__ b_ih)
{
    __shared__ float tile[32][33];
    const int bx = blockIdx.x;
    const int tid = threadIdx.x;

    if (bx < 1024) {
        const float4* src = (const float4*)Wlg;
        uint2* dh = (uint2*)g_Wlg_hi;
        uint2* dl = (uint2*)g_Wlg_lo;
        for (int i = bx * 256 + tid; i < ZD * ZD / 4; i += 1024 * 256) {
            float4 v = src[i];
            uint32_t h0 = pack_bf(v.x, v.y), h1 = pack_bf(v.z, v.w);
            float lx = v.x - __bfloat162float(__float2bfloat16(v.x));
            float ly = v.y - __bfloat162float(__float2bfloat16(v.y));
            float lz = v.z - __bfloat162float(__float2bfloat16(v.z));
            float lw = v.w - __bfloat162float(__float2bfloat16(v.w));
            dh[i] = make_uint2(h0, h1);
            dl[i] = make_uint2(pack_bf(lx, ly), pack_bf(lz, lw));
        }
    } else if (bx < 13312) {
        const int id = bx - 1024;
        const int tbx = id % (G3 / 32);
        const int tby = id / (G3 / 32);
        const int tx = tid & 31, ty = tid >> 5;
        const int x = tbx * 32 + tx;
        const int y0 = tby * 32;
        #pragma unroll
        for (int j = ty; j < 32; j += 8)
            tile[j][tx] = Wih[(size_t)(y0 + j) * G3 + x];
        __syncthreads();
        const int k = tby * 32 + tx;
        const int n0 = tbx * 32;
        #pragma unroll
        for (int j = ty; j < 32; j += 8) {
            float v = tile[tx][j];
            __nv_bfloat16 h = __float2bfloat16(v);
            size_t o = (size_t)(n0 + j) * ZD + k;
            g_WihT_hi[o] = h;
            g_WihT_lo[o] = __float2bfloat16(v - __bfloat162float(h));
        }
    } else if (bx < 14336) {
        const int b0 = bx - 13312;
        const float4* src = (const float4*)z;
        uint2* dh = (uint2*)g_zhi;
        uint2* dl = (uint2*)g_zlo;
        for (int i = b0 * 256 + tid; i < ROWS * ZD / 4; i += 1024 * 256) {
            float4 v = src[i];
            uint32_t h0 = pack_bf(v.x, v.y), h1 = pack_bf(v.z, v.w);
            float lx = v.x - __bfloat162float(__float2bfloat16(v.x));
            float ly = v.y - __bfloat162float(__float2bfloat16(v.y));
            float lz = v.z - __bfloat162float(__float2bfloat16(v.z));
            float lw = v.w - __bfloat162float(__float2bfloat16(v.w));
            dh[i] = make_uint2(h0, h1);
            dl[i] = make_uint2(pack_bf(lx, ly), pack_bf(lz, lw));
        }
    } else {
        __shared__ float red[4][64];
        const int bid = bx - 14336;
        const int tx = tid & 63;
        const int ty = tid >> 6;
        const int o = bid * 64 + tx;
        float acc = 0.0f;
        for (int m = ty; m < ZD; m += 4)
            acc = fmaf(b_lg[m], Wih[(size_t)m * G3 + o], acc);
        red[ty][tx] = acc;
        __syncthreads();
        if (ty == 0)
            g_bcomb[o] = b_ih[o] + red[0][tx] + red[1][tx] + red[2][tx] + red[3][tx];
    }
}

// ---------------- split-bf16 mma.sync GEMM (128x256 tile, 512 thr) ----------
#define MMK       ZD
#define BKC       32
#define NC        (MMK / BKC)      // 128 chunks
#define ROWB      80
#define A_TILEB   (128 * ROWB)
#define B_TILEB   (256 * ROWB)
#define STAGEB    (2 * A_TILEB + 2 * B_TILEB)  // 61440
#define NSTAGE    3
#define MM_SMEM   (NSTAGE * STAGEB)            // 184320

__global__ __launch_bounds__(512) void mm_mma_kernel(
    const __nv_bfloat16* __restrict__ Ahi, const __nv_bfloat16* __restrict__ Alo,
    const __nv_bfloat16* __restrict__ Bhi, const __nv_bfloat16* __restrict__ Blo,
    const float* __restrict__ bias,
    __nv_bfloat16* __restrict__ Chi, __nv_bfloat16* __restrict__ Clo,
    int Nglob, int which)
{
    extern __shared__ char smem[];
    const uint32_t sb = smem_u32(smem);
    const int tid  = threadIdx.x;
    const int wid  = tid >> 5;
    const int lane = tid & 31;
    const int wm   = wid & 3;
    const int wn   = wid >> 2;

    const size_t mBase = (size_t)blockIdx.y * 128;
    const size_t nBase = (size_t)blockIdx.x * 256;

    const __nv_bfloat16* tp[4] = { Ahi, Alo, Bhi, Blo };
    const size_t rb[4]  = { mBase, mBase, nBase, nBase };
    const uint32_t toff[4] = { 0, A_TILEB, 2 * A_TILEB, 2 * A_TILEB + B_TILEB };

    const __nv_bfloat16* srcs[6];
    uint32_t dsts[6];
    #pragma unroll
    for (int i = 0; i < 6; ++i) {
        const int u   = tid + 512 * i;
        const int r   = u >> 2;
        const int seg = u & 3;
        int tile, lrow;
        if (r < 128)      { tile = 0; lrow = r; }
        else if (r < 256) { tile = 1; lrow = r - 128; }
        else if (r < 512) { tile = 2; lrow = r - 256; }
        else              { tile = 3; lrow = r - 512; }
        srcs[i] = tp[tile] + (rb[tile] + lrow) * MMK + seg * 8;
        dsts[i] = toff[tile] + (uint32_t)lrow * ROWB + seg * 16;
    }

    float acc[2][8][4];
    #pragma unroll
    for (int a = 0; a < 2; ++a)
        #pragma unroll
        for (int b = 0; b < 8; ++b)
            #pragma unroll
            for (int c = 0; c < 4; ++c) acc[a][b][c] = 0.0f;

    const int arow = wm * 32 + (lane & 7) + 8 * ((lane >> 3) & 1);
    const int brow = wn * 64 + (lane & 7) + 8 * (lane >> 4);
    const int acol_half = lane >> 4;
    const int bcol_half = (lane >> 3) & 1;

    #pragma unroll
    for (int i = 0; i < 6; ++i) cp16(sb + 0 * STAGEB + dsts[i], srcs[i]);
    cp_commit();
    #pragma unroll
    for (int i = 0; i < 6; ++i) cp16(sb + 1 * STAGEB + dsts[i], srcs[i] + BKC);
    cp_commit();
    cp_wait<1>();
    __syncthreads();

    int s = 0;
    for (int c = 0; c < NC; ++c) {
        const uint32_t stB = sb + s * STAGEB;
        const int pf = (s + 2 >= NSTAGE) ? s + 2 - NSTAGE : s + 2;
        const uint32_t pfB = sb + pf * STAGEB;
        const bool do_pf = (c + 2 < NC);
        const size_t pfk = (size_t)(c + 2) * BKC;

        const uint32_t AhB = stB;
        const uint32_t AlB = stB + A_TILEB;
        const uint32_t BhB = stB + 2 * A_TILEB;
        const uint32_t BlB = stB + 2 * A_TILEB + B_TILEB;

        #pragma unroll
        for (int ks = 0; ks < 2; ++ks) {
            const uint32_t acolb = (uint32_t)(16 * ks + 8 * acol_half) * 2;
            const uint32_t bcolb = (uint32_t)(16 * ks + 8 * bcol_half) * 2;
            uint32_t Ah0[4], Ah1[4], Al0[4], Al1[4];
            ldsm_x4(Ah0, AhB + (uint32_t)arow * ROWB + acolb);
            ldsm_x4(Ah1, AhB + (uint32_t)(arow + 16) * ROWB + acolb);
            ldsm_x4(Al0, AlB + (uint32_t)arow * ROWB + acolb);
            ldsm_x4(Al1, AlB + (uint32_t)(arow + 16) * ROWB + acolb);
            #pragma unroll
            for (int nb = 0; nb < 4; ++nb) {
                const uint32_t brb = (uint32_t)(brow + nb * 16) * ROWB + bcolb;
                uint32_t bh[4], bl[4];
                ldsm_x4(bh, BhB + brb);
                ldsm_x4(bl, BlB + brb);
                {
                    const int g = ks * 4 + nb;
                    if (g < 6 && do_pf) cp16(pfB + dsts[g], srcs[g] + pfk);
                }
                mma16816(acc[0][2 * nb],     Ah0, bh[0], bh[1]);
                mma16816(acc[0][2 * nb + 1], Ah0, bh[2], bh[3]);
                mma16816(acc[1][2 * nb],     Ah1, bh[0], bh[1]);
                mma16816(acc[1][2 * nb + 1], Ah1, bh[2], bh[3]);
                mma16816(acc[0][2 * nb],     Ah0, bl[0], bl[1]);
                mma16816(acc[0][2 * nb + 1], Ah0, bl[2], bl[3]);
                mma16816(acc[1][2 * nb],     Ah1, bl[0], bl[1]);
                mma16816(acc[1][2 * nb + 1], Ah1, bl[2], bl[3]);
                mma16816(acc[0][2 * nb],     Al0, bh[0], bh[1]);
                mma16816(acc[0][2 * nb + 1], Al0, bh[2], bh[3]);
                mma16816(acc[1][2 * nb],     Al1, bh[0], bh[1]);
                mma16816(acc[1][2 * nb + 1], Al1, bh[2], bh[3]);
            }
        }
        cp_commit();
        cp_wait<1>();
        __syncthreads();
        s = (s + 1 == NSTAGE) ? 0 : s + 1;
    }

    const int rrow = (lane >> 2);
    const int ccol = 2 * (lane & 3);
    #pragma unroll
    for (int mi = 0; mi < 2; ++mi) {
        const size_t r0 = mBase + wm * 32 + mi * 16 + rrow;
        #pragma unroll
        for (int n8 = 0; n8 < 8; ++n8) {
            const int col = (int)nBase + wn * 64 + n8 * 8 + ccol;
            const float bz0 = __ldg(&bias[col]);
            const float bz1 = __ldg(&bias[col + 1]);
            const float* f = acc[mi][n8];
            if (which == 0) {
                #pragma unroll
                for (int h = 0; h < 2; ++h) {
                    const size_t r = r0 + 8 * h;
                    float v0 = f[2 * h]     + bz0;
                    float v1 = f[2 * h + 1] + bz1;
                    __nv_bfloat16 h0 = __float2bfloat16(v0);
                    __nv_bfloat16 h1 = __float2bfloat16(v1);
                    __nv_bfloat16 l0 = __float2bfloat16(v0 - __bfloat162float(h0));
                    __nv_bfloat16 l1 = __float2bfloat16(v1 - __bfloat162float(h1));
                    uint32_t hp = ((uint32_t)__bfloat16_as_ushort(h1) << 16) |
                                  (uint32_t)__bfloat16_as_ushort(h0);
                    uint32_t lp = ((uint32_t)__bfloat16_as_ushort(l1) << 16) |
                                  (uint32_t)__bfloat16_as_ushort(l0);
                    *(uint32_t*)&Chi[r * (size_t)Nglob + col] = hp;
                    *(uint32_t*)&Clo[r * (size_t)Nglob + col] = lp;
                }
            } else {
                #pragma unroll
                for (int h = 0; h < 2; ++h) {
                    const size_t r = r0 + 8 * h;
                    float2 v = make_float2(f[2 * h] + bz0, f[2 * h + 1] + bz1);
                    *(float2*)&g_GI[r * (size_t)Nglob + col] = v;
                }
            }
        }
    }
}

// ---------------- persistent GRU scan ---------------------------------------
// Each warp: 2 hidden units x 4 batches (halves smem crossbar traffic vs
// 1 unit x 8 batches). Flat R15 barrier (measured-best).
__global__ __launch_bounds__(256, 1) void gru_scan_kernel(
    const float* __restrict__ W_hh, const float* __restrict__ b_hh)
{
    __shared__ alignas(16) float sh[HID * BATCH];    // h_prev, [k][b]
    __shared__ unsigned s_sense;
    const int tid  = threadIdx.x;
    const int lane = tid & 31;
    const int Wg   = blockIdx.x * 8 + (tid >> 5);    // 0..1023
    const int j0   = (Wg >> 1) * 2;                  // unit pair {j0, j0+1}
    const int half = Wg & 1;                         // batch half: [4h, 4h+4)

    // weights -> registers: 2 units x 3 gates x 32 (full unroll, no local mem)
    float wr0[32], wu0[32], wn0[32], wr1[32], wu1[32], wn1[32];
    #pragma unroll
    for (int it = 0; it < 32; ++it) {
        const size_t k = (size_t)(lane + 32 * it) * G3;
        wr0[it] = __ldg(&W_hh[k + j0]);
        wr1[it] = __ldg(&W_hh[k + j0 + 1]);
        wu0[it] = __ldg(&W_hh[k + HID + j0]);
        wu1[it] = __ldg(&W_hh[k + HID + j0 + 1]);
        wn0[it] = __ldg(&W_hh[k + 2 * HID + j0]);
        wn1[it] = __ldg(&W_hh[k + 2 * HID + j0 + 1]);
    }
    // final-update constants (meaningful for lanes 0-7)
    const int jf = j0 + ((lane >> 2) & 1);
    const int bf = half * 4 + (lane & 3);
    const float bhr = b_hh[jf];
    const float bhu = b_hh[HID + jf];
    const float bhn = b_hh[2 * HID + jf];

    if (tid == 0) s_sense = g_bar_flag;
    for (int i = tid; i < HID * BATCH; i += 256) sh[i] = 0.0f;   // h0 = 0
    __syncthreads();
    unsigned sense = s_sense;

    // prefetch gi for t = 0
    float pir = 0.f, piu = 0.f, pin = 0.f;
    if (lane < 8) {
        const float* gi = g_GI + (size_t)bf * WIN * G3;
        pir = gi[jf]; piu = gi[HID + jf]; pin = gi[2 * HID + jf];
    }

    for (int t = 0; t < WIN; ++t) {
        // A[u*6 + g*2 + q]: u in {0,1}, g in {r,u,n}, q: batch pair (0,1)/(2,3)
        ull A[12];
        #pragma unroll
        for (int p = 0; p < 12; ++p) A[p] = 0ull;

        #pragma unroll
        for (int it = 0; it < 32; ++it) {
            const int k = lane + 32 * it;
            const ulonglong2 hv = *(const ulonglong2*)&sh[k * 8 + half * 4];
            const ull sr0 = splat2(wr0[it]);
            const ull su0 = splat2(wu0[it]);
            const ull sn0 = splat2(wn0[it]);
            const ull sr1 = splat2(wr1[it]);
            const ull su1 = splat2(wu1[it]);
            const ull sn1 = splat2(wn1[it]);
            ffma2(A[0],  sr0, hv.x); ffma2(A[1],  sr0, hv.y);
            ffma2(A[2],  su0, hv.x); ffma2(A[3],  su0, hv.y);
            ffma2(A[4],  sn0, hv.x); ffma2(A[5],  sn0, hv.y);
            ffma2(A[6],  sr1, hv.x); ffma2(A[7],  sr1, hv.y);
            ffma2(A[8],  su1, hv.x); ffma2(A[9],  su1, hv.y);
            ffma2(A[10], sn1, hv.x); ffma2(A[11], sn1, hv.y);
        }

        // combos c = u*4 + bi (bi = batch within half)
        float a0[8], a1[8], a2[8];
        unpack2(A[0],  a0[0], a0[1]); unpack2(A[1],  a0[2], a0[3]);
        unpack2(A[6],  a0[4], a0[5]); unpack2(A[7],  a0[6], a0[7]);
        unpack2(A[2],  a1[0], a1[1]); unpack2(A[3],  a1[2], a1[3]);
        unpack2(A[8],  a1[4], a1[5]); unpack2(A[9],  a1[6], a1[7]);
        unpack2(A[4],  a2[0], a2[1]); unpack2(A[5],  a2[2], a2[3]);
        unpack2(A[10], a2[4], a2[5]); unpack2(A[11], a2[6], a2[7]);

        // stage A: butterfly within 8-lane groups (offsets 1,2,4)
        #pragma unroll
        for (int off = 1; off <= 4; off <<= 1) {
            #pragma unroll
            for (int b = 0; b < 8; ++b) {
                a0[b] += __shfl_xor_sync(0xffffffffu, a0[b], off);
                a1[b] += __shfl_xor_sync(0xffffffffu, a1[b], off);
                a2[b] += __shfl_xor_sync(0xffffffffu, a2[b], off);
            }
        }
        // stage B: pick combo c = lane&7, then reduce across octets
        const int bs = lane & 7;
        float hr = sel8(a0, bs);
        float hu = sel8(a1, bs);
        float hn = sel8(a2, bs);
        hr += __shfl_xor_sync(0xffffffffu, hr, 8);
        hu += __shfl_xor_sync(0xffffffffu, hu, 8);
        hn += __shfl_xor_sync(0xffffffffu, hn, 8);
        hr += __shfl_xor_sync(0xffffffffu, hr, 16);
        hu += __shfl_xor_sync(0xffffffffu, hu, 16);
        hn += __shfl_xor_sync(0xffffffffu, hn, 16);

        if (lane < 8) {
            // lane -> combo: u = lane>>2 (matches jf), bi = lane&3 (matches bf)
            hr += bhr; hu += bhu; hn += bhn;
            const float rg = 1.0f / (1.0f + expf(-(pir + hr)));
            const float ug = 1.0f / (1.0f + expf(-(piu + hu)));
            const float ng = tanhf(fmaf(rg, hn, pin));
            const float hp = sh[jf * 8 + bf];
            const float hnew = (1.0f - ug) * ng + ug * hp;
            g_hT[t & 1][jf * 8 + bf] = hnew;
            g_H[((size_t)bf * WIN + t) * HID + jf] = hnew;
        }
        __syncthreads();

        // prefetch gi for step t+1 (independent of the barrier)
        float nir = 0.f, niu = 0.f, nin = 0.f;
        if (t + 1 < WIN && lane < 8) {
            const float* gi = g_GI + ((size_t)bf * WIN + t + 1) * G3;
            nir = gi[jf]; niu = gi[HID + jf]; nin = gi[2 * HID + jf];
        }

        // R15 flat grid barrier (sense-reversing; tight spin)
        if (tid == 0) {
            __threadfence();
            const unsigned old = atomicAdd(&g_bar_ctr, 1u);
            if (old == NCTA_SCAN - 1) {
                g_bar_ctr = 0;
                __threadfence();
                g_bar_flag = sense ^ 1u;
            }
            while (g_bar_flag == sense) { }
            __threadfence();
        }
        __syncthreads();
        sense ^= 1u;

        if (t + 1 < WIN) {
            const float4* src = (const float4*)g_hT[t & 1];
            float4* dst = (float4*)sh;
            #pragma unroll
            for (int i = tid; i < HID * BATCH / 4; i += 256) dst[i] = src[i];
            __syncthreads();
        }
        pir = nir; piu = niu; pin = nin;
    }
}

// ---------------- dense + heads (unchanged) --------------------------------
__global__ __launch_bounds__(128) void dense_kernel(
    const float* __restrict__ Wd, const float* __restrict__ bd)
{
    __shared__ float sh[8 * HID];
    const int r0 = blockIdx.x * 8;
    for (int i = threadIdx.x; i < 8 * HID; i += 128)
        sh[i] = g_H[(size_t)r0 * HID + i];
    __syncthreads();

    const int c = threadIdx.x;
    if (c < DEN) {
        float acc[8];
        #pragma unroll
        for (int i = 0; i < 8; ++i) acc[i] = bd[c];
        #pragma unroll 4
        for (int k = 0; k < HID; ++k) {
            const float w = Wd[k * DEN + c];
            #pragma unroll
            for (int i = 0; i < 8; ++i)
                acc[i] = fmaf(sh[i * HID + k], w, acc[i]);
        }
        #pragma unroll
        for (int i = 0; i < 8; ++i)
            g_D[(size_t)(r0 + i) * DEN + c] = acc[i];
    }
}

__global__ __launch_bounds__(128) void heads_kernel(
    const float* __restrict__ W_mu, const float* __restrict__ b_mu,
    const float* __restrict__ W_sg, const float* __restrict__ b_sg,
    const float* __restrict__ noise, float* __restrict__ out)
{
    __shared__ float sh[16 * DEN];
    const int r0 = blockIdx.x * 16;
    for (int i = threadIdx.x; i < 16 * DEN; i += 128)
        sh[i] = g_D[(size_t)r0 * DEN + i];
    __syncthreads();

    const int c = threadIdx.x;
    if (c < OUT_D) {
        float am[16], as[16];
        #pragma unroll
        for (int i = 0; i < 16; ++i) { am[i] = b_mu[c]; as[i] = b_sg[c]; }
        #pragma unroll 2
        for (int k = 0; k < DEN; ++k) {
            const float wm = W_mu[k * OUT_D + c];
            const float ws = W_sg[k * OUT_D + c];
            #pragma unroll
            for (int i = 0; i < 16; ++i) {
                const float d = sh[i * DEN + k];
                am[i] = fmaf(d, wm, am[i]);
                as[i] = fmaf(d, ws, as[i]);
            }
        }
        #pragma unroll
        for (int i = 0; i < 16; ++i) {
            const size_t r = (size_t)(r0 + i);
            const float x = as[i];
            const float sp = fmaxf(x, 0.0f) + log1pf(expf(-fabsf(x)));
            out[r * OUT_D + c] = fmaf(sp, noise[r * OUT_D + c], am[i]);
        }
    }
}

// ---------------------------------------------------------------------------
extern "C" void kernel_launch(void* const* d_in, const int* in_sizes, int n_in,
                              void* d_out, int out_size)
{
    const float* z        = (const float*)d_in[0];
    const float* noise    = (const float*)d_in[1];
    const float* W_lgssm  = (const float*)d_in[2];
    const float* b_lgssm  = (const float*)d_in[3];
    const float* W_ih     = (const float*)d_in[4];
    const float* b_ih     = (const float*)d_in[5];
    const float* W_hh     = (const float*)d_in[6];
    const float* b_hh     = (const float*)d_in[7];
    const float* W_dense  = (const float*)d_in[8];
    const float* b_dense  = (const float*)d_in[9];
    const float* W_mu     = (const float*)d_in[10];
    const float* b_mu     = (const float*)d_in[11];
    const float* W_sigma  = (const float*)d_in[12];
    const float* b_sigma  = (const float*)d_in[13];
    float* out = (float*)d_out;

    static int attr_done = 0;
    if (!attr_done) {
        cudaFuncSetAttribute(mm_mma_kernel,
                             cudaFuncAttributeMaxDynamicSharedMemorySize, MM_SMEM);
        attr_done = 1;
    }

    __nv_bfloat16 *p_zhi, *p_zlo, *p_Wlg_hi, *p_Wlg_lo, *p_Wih_hi, *p_Wih_lo;
    __nv_bfloat16 *p_WcT_hi, *p_WcT_lo;
    float *p_bcomb, *p_zb;
    cudaGetSymbolAddress((void**)&p_zhi,    g_zhi);
    cudaGetSymbolAddress((void**)&p_zlo,    g_zlo);
    cudaGetSymbolAddress((void**)&p_Wlg_hi, g_Wlg_hi);
    cudaGetSymbolAddress((void**)&p_Wlg_lo, g_Wlg_lo);
    cudaGetSymbolAddress((void**)&p_Wih_hi, g_WihT_hi);
    cudaGetSymbolAddress((void**)&p_Wih_lo, g_WihT_lo);
    cudaGetSymbolAddress((void**)&p_WcT_hi, g_WcT_hi);
    cudaGetSymbolAddress((void**)&p_WcT_lo, g_WcT_lo);
    cudaGetSymbolAddress((void**)&p_bcomb,  g_bcomb);
    cudaGetSymbolAddress((void**)&p_zb,     g_zb);

    // 1: merged prep (W_lgssm split | W_ih transpose+split | z split | bcomb)
    prep_kernel<<<PREP_BLOCKS, 256>>>(W_lgssm, W_ih, z, b_lgssm, b_ih);
    // 2: fold GEMM: W_combT = (W_lgssm @ W_ih)^T  -> bf16 hi/lo
    mm_mma_kernel<<<dim3(ZD / 256, G3 / 128), 512, MM_SMEM>>>(
        p_Wih_hi, p_Wih_lo, p_Wlg_hi, p_Wlg_lo, p_zb, p_WcT_hi, p_WcT_lo, ZD, 0);
    // 3: data GEMM: GI = z @ W_comb + b_comb -> fp32
    mm_mma_kernel<<<dim3(G3 / 256, ROWS / 128), 512, MM_SMEM>>>(
        p_zhi, p_zlo, p_WcT_hi, p_WcT_lo, p_bcomb, nullptr, nullptr, G3, 1);
    // 4: persistent GRU scan (ncu capture slot)
    gru_scan_kernel<<<NCTA_SCAN, 256>>>(W_hh, b_hh);
    // 5-6: deferred output path
    dense_kernel<<<ROWS / 8, 128>>>(W_dense, b_dense);
    heads_kernel<<<ROWS / 16, 128>>>(W_mu, b_mu, W_sigma, b_sigma, noise, out);
}